// round 1
// baseline (speedup 1.0000x reference)
#include <cuda_runtime.h>
#include <cuda_bf16.h>

// ============================================================================
// TensorizedEmbedding_order4: out[t, b*32+d] = sum_r out1[row(t), b, r] * out2[r, col(t), d]
// with v = x[t] in [0, 32000), row = v/160, col = v%160.
//
// Strategy: v indexes a 200x160 grid exactly -> precompute the FULL table
//   C[4800, 5120] = A[4800, 64] @ B[64, 5120]   (one GEMM, 3.15 GFLOP)
// where A[(row*24+b), r] = out1[row, b, r],  B[r, (col*32+d)] = out2[r, col, d].
// Then the per-token work is a pure gather:
//   out[t][b*32+d] = C[(row*24+b)*5120 + col*32 + d]
// ============================================================================

#define A_ROWS 4800   // 200 rows * 24 (a*6+b)
#define KDIM   64
#define NCOLS  5120   // 160 cols * 32 (a*8+b)

__device__ float g_A[A_ROWS * KDIM];          // 1.2 MB
__device__ float g_B[KDIM * NCOLS];           // 1.3 MB
__device__ float g_C[A_ROWS * NCOLS];         // 98.3 MB table

// ----------------------------------------------------------------------------
// out1[n,m,a,b,r] = sum_q f0[0,n,a,q] * f1[q,m,b,r]
// stored as g_A[((n*25+m)*24 + a*6 + b)*64 + r]
// grid = 4800 blocks (one output row), 64 threads (r)
// ----------------------------------------------------------------------------
__global__ void build_A_kernel(const float* __restrict__ f0,
                               const float* __restrict__ f1) {
    int rowid = blockIdx.x;              // (n*25+m)*24 + a*6 + b
    int r = threadIdx.x;
    int b = rowid % 6;
    int t = rowid / 6;
    int a = t % 4;  t /= 4;
    int m = t % 25;
    int n = t / 25;
    const float* f0p = f0 + (n * 4 + a) * 64;          // f0[0,n,a,:]
    const float* f1p = f1 + (m * 6 + b) * 64 + r;      // f1[q,m,b,r], q-stride 9600
    float acc = 0.f;
#pragma unroll
    for (int q = 0; q < 64; ++q)
        acc = fmaf(f0p[q], f1p[q * 9600], acc);
    g_A[rowid * 64 + r] = acc;
}

// ----------------------------------------------------------------------------
// out2[q,n,m,a,b] = sum_s f2[q,n,a,s] * f3[s,m,b,0]
// stored as g_B[q*5120 + (n*8+m)*32 + a*8 + b]
// grid = 5120 blocks (q*80 + n*4 + a), 64 threads (m*8+b)
// ----------------------------------------------------------------------------
__global__ void build_B_kernel(const float* __restrict__ f2,
                               const float* __restrict__ f3) {
    int id = blockIdx.x;                 // (q*20+n)*4 + a
    int a = id % 4;
    int t = id / 4;
    int n = t % 20;
    int q = t / 20;
    int mb = threadIdx.x;                // m*8 + b
    const float* f2p = f2 + id * 64;     // f2[q,n,a,:]
    const float* f3p = f3 + mb;          // f3[s,m,b], s-stride 64
    float acc = 0.f;
#pragma unroll
    for (int s = 0; s < 64; ++s)
        acc = fmaf(f2p[s], f3p[s * 64], acc);
    int m = mb >> 3, b = mb & 7;
    g_B[q * 5120 + (n * 8 + m) * 32 + a * 8 + b] = acc;
}

// ----------------------------------------------------------------------------
// SGEMM: C[4800,5120] = A[4800,64] @ B[64,5120].  K=64 fits in one smem slab.
// Block tile 64x128, 128 threads, 8x8 register tile per thread.
// Static smem = 16KB (As) + 32KB (Bs) = exactly 48KB.
// ----------------------------------------------------------------------------
__global__ void __launch_bounds__(128) gemm_kernel() {
    __shared__ float As[64][64];    // [k][m]  (transposed for vector LDS)
    __shared__ float Bs[64][128];   // [k][n]
    int tid = threadIdx.x;
    int bm = blockIdx.y * 64;
    int bn = blockIdx.x * 128;

    // A tile: 1024 float4. k4-major thread mapping -> conflict-free smem stores
    // (gmem side is strided 256B/thread but A is tiny and L2-hot: 40x reuse).
#pragma unroll
    for (int i = 0; i < 8; ++i) {
        int e  = tid + i * 128;        // float4 index in tile
        int m  = e & 63;
        int k4 = e >> 6;
        float4 v = *(const float4*)(g_A + (bm + m) * 64 + k4 * 4);
        As[k4 * 4 + 0][m] = v.x;
        As[k4 * 4 + 1][m] = v.y;
        As[k4 * 4 + 2][m] = v.z;
        As[k4 * 4 + 3][m] = v.w;
    }
    // B tile: 2048 float4, fully coalesced, direct layout.
#pragma unroll
    for (int i = 0; i < 16; ++i) {
        int e  = tid + i * 128;
        int k  = e >> 5;
        int n4 = e & 31;
        *(float4*)(&Bs[k][n4 * 4]) = *(const float4*)(g_B + k * 5120 + bn + n4 * 4);
    }
    __syncthreads();

    int tx = tid & 15;      // n direction: 16 * 8 = 128
    int ty = tid >> 4;      // m direction:  8 * 8 =  64
    float acc[8][8];
#pragma unroll
    for (int i = 0; i < 8; ++i)
#pragma unroll
        for (int j = 0; j < 8; ++j) acc[i][j] = 0.f;

#pragma unroll 8
    for (int k = 0; k < 64; ++k) {
        float a[8], b[8];
        *(float4*)(a)     = *(const float4*)(&As[k][ty * 8]);
        *(float4*)(a + 4) = *(const float4*)(&As[k][ty * 8 + 4]);
        *(float4*)(b)     = *(const float4*)(&Bs[k][tx * 8]);
        *(float4*)(b + 4) = *(const float4*)(&Bs[k][tx * 8 + 4]);
#pragma unroll
        for (int i = 0; i < 8; ++i)
#pragma unroll
            for (int j = 0; j < 8; ++j)
                acc[i][j] = fmaf(a[i], b[j], acc[i][j]);
    }

#pragma unroll
    for (int i = 0; i < 8; ++i) {
        float* cp = g_C + (long)(bm + ty * 8 + i) * 5120 + bn + tx * 8;
        *(float4*)(cp)     = make_float4(acc[i][0], acc[i][1], acc[i][2], acc[i][3]);
        *(float4*)(cp + 4) = make_float4(acc[i][4], acc[i][5], acc[i][6], acc[i][7]);
    }
}

// ----------------------------------------------------------------------------
// Gather: out[t][b*32+d] = C[(row*24+b)*5120 + col*32+d], v = x[t].
// One block per token, 192 threads = 192 float4 = 768 floats.
// Both the 24x(128B) reads and the 3KB write are fully coalesced.
// ----------------------------------------------------------------------------
__global__ void gather_kernel(const int* __restrict__ x,
                              float4* __restrict__ out) {
    int t = blockIdx.x;
    int j = threadIdx.x;                 // 0..191
    int v = __ldg(x + t);
    int row = v / 160;
    int col = v - row * 160;
    int b  = j >> 3;                     // 0..23
    int d4 = j & 7;                      // 0..7 (float4 within 32 d)
    const float* cp = g_C + (long)(row * 24 + b) * 5120 + col * 32 + d4 * 4;
    out[(long)t * 192 + j] = *(const float4*)cp;
}

// ----------------------------------------------------------------------------
// Inputs (metadata order): x[16,4096] int32, f0[1,8,4,64], f1[64,25,6,64],
// f2[64,20,4,64], f3[64,8,8,1] all fp32.  Output: [16,4096,768] fp32.
// ----------------------------------------------------------------------------
extern "C" void kernel_launch(void* const* d_in, const int* in_sizes, int n_in,
                              void* d_out, int out_size) {
    const int*   x  = (const int*)  d_in[0];
    const float* f0 = (const float*)d_in[1];
    const float* f1 = (const float*)d_in[2];
    const float* f2 = (const float*)d_in[3];
    const float* f3 = (const float*)d_in[4];

    build_A_kernel<<<A_ROWS, 64>>>(f0, f1);
    build_B_kernel<<<NCOLS, 64>>>(f2, f3);

    dim3 grid(NCOLS / 128, A_ROWS / 64);   // 40 x 75
    gemm_kernel<<<grid, 128>>>();

    gather_kernel<<<16 * 4096, 192>>>(x, (float4*)d_out);
}

// round 4
// speedup vs baseline: 1.1025x; 1.1025x over previous
#include <cuda_runtime.h>
#include <cuda_bf16.h>

// ============================================================================
// TensorizedEmbedding_order4: out[t, b*32+d] = sum_r out1[row(t), b, r] * out2[r, col(t), d]
// v = x[t] in [0, 32000), row = v/160, col = v%160.
//
// Table strategy: C[4800, 5120] = A[4800, 64] @ B[64, 5120] covers all 32000
// possible v exactly; per-token work is then a pure gather.
//
//  - GEMM inner loop uses packed fma.rn.f32x2 -> 2x fp32 FMA rate
//    (scalar 3-reg FFMA is half-rate: rt_SMSP=2).
//  - Gather: 32 threads/token, 6 independent LDG.128 per thread (MLP 6),
//    __stcs streaming output writes so g_C stays resident in L2.
// ============================================================================

#define A_ROWS 4800   // 200 rows * 24 (a*6+b)
#define KDIM   64
#define NCOLS  5120   // 160 cols * 32 (a*8+b)

__device__ float g_A[A_ROWS * KDIM];          // 1.2 MB
__device__ float g_B[KDIM * NCOLS];           // 1.3 MB
__device__ float g_C[A_ROWS * NCOLS];         // 98.3 MB table

// ----------------------------------------------------------------------------
// out1[n,m,a,b,r] = sum_q f0[0,n,a,q] * f1[q,m,b,r]
// g_A[((n*25+m)*24 + a*6 + b)*64 + r]
// ----------------------------------------------------------------------------
__global__ void build_A_kernel(const float* __restrict__ f0,
                               const float* __restrict__ f1) {
    int rowid = blockIdx.x;              // (n*25+m)*24 + a*6 + b
    int r = threadIdx.x;
    int b = rowid % 6;
    int t = rowid / 6;
    int a = t % 4;  t /= 4;
    int m = t % 25;
    int n = t / 25;
    const float* f0p = f0 + (n * 4 + a) * 64;          // f0[0,n,a,:]
    const float* f1p = f1 + (m * 6 + b) * 64 + r;      // f1[q,m,b,r], q-stride 9600
    float acc = 0.f;
#pragma unroll
    for (int q = 0; q < 64; ++q)
        acc = fmaf(f0p[q], f1p[q * 9600], acc);
    g_A[rowid * 64 + r] = acc;
}

// ----------------------------------------------------------------------------
// out2[q,n,m,a,b] = sum_s f2[q,n,a,s] * f3[s,m,b,0]
// g_B[q*5120 + (n*8+m)*32 + a*8 + b]
// ----------------------------------------------------------------------------
__global__ void build_B_kernel(const float* __restrict__ f2,
                               const float* __restrict__ f3) {
    int id = blockIdx.x;                 // (q*20+n)*4 + a
    int a = id % 4;
    int t = id / 4;
    int n = t % 20;
    int q = t / 20;
    int mb = threadIdx.x;                // m*8 + b
    const float* f2p = f2 + id * 64;     // f2[q,n,a,:]
    const float* f3p = f3 + mb;          // f3[s,m,b], s-stride 64
    float acc = 0.f;
#pragma unroll
    for (int s = 0; s < 64; ++s)
        acc = fmaf(f2p[s], f3p[s * 64], acc);
    int m = mb >> 3, b = mb & 7;
    g_B[q * 5120 + (n * 8 + m) * 32 + a * 8 + b] = acc;
}

// ----------------------------------------------------------------------------
// SGEMM with packed f32x2 FMAs: C[4800,5120] = A[4800,64] @ B[64,5120].
// Block tile 64x128, 128 threads, 8x8 register tile (acc paired along n).
// Static smem = 16KB (As) + 32KB (Bs) = 48KB.
// ----------------------------------------------------------------------------
__global__ void __launch_bounds__(128) gemm_kernel() {
    __shared__ float As[64][64];    // [k][m]
    __shared__ float Bs[64][128];   // [k][n]
    int tid = threadIdx.x;
    int bm = blockIdx.y * 64;
    int bn = blockIdx.x * 128;

#pragma unroll
    for (int i = 0; i < 8; ++i) {
        int e  = tid + i * 128;        // float4 index in A tile
        int m  = e & 63;
        int k4 = e >> 6;
        float4 v = *(const float4*)(g_A + (bm + m) * 64 + k4 * 4);
        As[k4 * 4 + 0][m] = v.x;
        As[k4 * 4 + 1][m] = v.y;
        As[k4 * 4 + 2][m] = v.z;
        As[k4 * 4 + 3][m] = v.w;
    }
#pragma unroll
    for (int i = 0; i < 16; ++i) {
        int e  = tid + i * 128;
        int k  = e >> 5;
        int n4 = e & 31;
        *(float4*)(&Bs[k][n4 * 4]) = *(const float4*)(g_B + k * 5120 + bn + n4 * 4);
    }
    __syncthreads();

    int tx = tid & 15;      // n direction: 16 * 8 = 128
    int ty = tid >> 4;      // m direction:  8 * 8 =  64

    // acc2[i][j] holds C[m=ty*8+i][n=tx*8+2j .. 2j+1] as packed f32x2
    unsigned long long acc2[8][4];
#pragma unroll
    for (int i = 0; i < 8; ++i)
#pragma unroll
        for (int j = 0; j < 4; ++j) acc2[i][j] = 0ULL;

#pragma unroll 8
    for (int k = 0; k < 64; ++k) {
        float a[8];
        unsigned long long b2[4];
        *(float4*)(a)      = *(const float4*)(&As[k][ty * 8]);
        *(float4*)(a + 4)  = *(const float4*)(&As[k][ty * 8 + 4]);
        *(float4*)(&b2[0]) = *(const float4*)(&Bs[k][tx * 8]);
        *(float4*)(&b2[2]) = *(const float4*)(&Bs[k][tx * 8 + 4]);

        unsigned long long a2[8];
#pragma unroll
        for (int i = 0; i < 8; ++i)
            asm("mov.b64 %0, {%1, %1};" : "=l"(a2[i]) : "f"(a[i]));
#pragma unroll
        for (int i = 0; i < 8; ++i)
#pragma unroll
            for (int j = 0; j < 4; ++j)
                asm("fma.rn.f32x2 %0, %1, %2, %3;"
                    : "=l"(acc2[i][j]) : "l"(a2[i]), "l"(b2[j]), "l"(acc2[i][j]));
    }

#pragma unroll
    for (int i = 0; i < 8; ++i) {
        float* cp = g_C + (long)(bm + ty * 8 + i) * 5120 + bn + tx * 8;
        const float* accf = (const float*)acc2[i];
        *(float4*)(cp)     = make_float4(accf[0], accf[1], accf[2], accf[3]);
        *(float4*)(cp + 4) = make_float4(accf[4], accf[5], accf[6], accf[7]);
    }
}

// ----------------------------------------------------------------------------
// Gather: out[t][b*32+d] = C[(row*24+b)*5120 + col*32+d], v = x[t].
// 8 tokens/block, 32 threads/token, 6 independent float4 loads per thread
// (MLP=6). Streaming stores (__stcs) keep g_C resident in L2.
// ----------------------------------------------------------------------------
__global__ void __launch_bounds__(256) gather_kernel(const int* __restrict__ x,
                                                     float4* __restrict__ out) {
    int tid  = threadIdx.x;
    int t    = blockIdx.x * 8 + (tid >> 5);   // token id
    int lane = tid & 31;
    int v = __ldg(x + t);
    int row = v / 160;
    int col = v - row * 160;
    const float* base = g_C + (long)row * 24 * 5120 + col * 32;
    float4* op = out + (long)t * 192;
#pragma unroll
    for (int i = 0; i < 6; ++i) {
        int j  = lane + i * 32;               // 0..191
        int b  = j >> 3;                      // 0..23
        int d4 = j & 7;                       // float4 within 32 d
        float4 val = *(const float4*)(base + b * 5120 + d4 * 4);
        __stcs(op + j, val);
    }
}

// ----------------------------------------------------------------------------
// Inputs (metadata order): x[16,4096] int32, f0[1,8,4,64], f1[64,25,6,64],
// f2[64,20,4,64], f3[64,8,8,1] fp32.  Output: [16,4096,768] fp32.
// ----------------------------------------------------------------------------
extern "C" void kernel_launch(void* const* d_in, const int* in_sizes, int n_in,
                              void* d_out, int out_size) {
    const int*   x  = (const int*)  d_in[0];
    const float* f0 = (const float*)d_in[1];
    const float* f1 = (const float*)d_in[2];
    const float* f2 = (const float*)d_in[3];
    const float* f3 = (const float*)d_in[4];

    build_A_kernel<<<A_ROWS, 64>>>(f0, f1);
    build_B_kernel<<<NCOLS, 64>>>(f2, f3);

    dim3 grid(NCOLS / 128, A_ROWS / 64);   // 40 x 75
    gemm_kernel<<<grid, 128>>>();

    gather_kernel<<<16 * 4096 / 8, 256>>>(x, (float4*)d_out);
}